// round 1
// baseline (speedup 1.0000x reference)
#include <cuda_runtime.h>

// Problem constants: x (8, 512, 4096) fp32; W* (512,512); b* (512,)
#define BB 8
#define CC 512
#define TT 4096
#define SCALE_F 0.125f   // 64^-0.5

// Scratch (allocation-free rule: __device__ globals)
__device__ float g_q[(size_t)BB * CC * TT];     // 64 MB
__device__ float g_k[(size_t)BB * CC * TT];     // 64 MB
__device__ float g_v[(size_t)BB * CC * TT];     // 64 MB
__device__ float g_dots[(size_t)BB * CC * CC];  // 8 MB

#define BM 128
#define BN 128
#define BK 8
#define PAD 4

// ---------------------------------------------------------------------------
// NN GEMM: C[m,n] = sum_k A[m,k] * B[k,n]  (+ optional bias[m])
// A: M x K row-major (lda = K), B: K x N row-major (ldb = N), C: M x N (ldc = N)
// Batched via blockIdx.z with element strides. M%128==0, N%128==0, K%8==0.
// ---------------------------------------------------------------------------
template <bool HAS_BIAS>
__global__ __launch_bounds__(256, 2) void gemm_nn_kernel(
    const float* __restrict__ A, size_t strideA,
    const float* __restrict__ Bm, size_t strideB,
    float* __restrict__ Cm, size_t strideC,
    const float* __restrict__ bias,
    int M, int N, int K)
{
    const float* Ab = A + (size_t)blockIdx.z * strideA;
    const float* Bb = Bm + (size_t)blockIdx.z * strideB;
    float*       Cb = Cm + (size_t)blockIdx.z * strideC;

    __shared__ float As[BK][BM + PAD];
    __shared__ float Bs[BK][BN + PAD];

    const int tid = threadIdx.x;            // 0..255
    const int m0 = blockIdx.y * BM;
    const int n0 = blockIdx.x * BN;

    const int aRow = tid >> 1;              // 0..127
    const int aSeg = (tid & 1) * 4;         // 0 or 4
    const int bRow = tid >> 5;              // 0..7
    const int bCol = (tid & 31) * 4;        // 0..124

    const int tx = tid & 15;                // col group
    const int ty = tid >> 4;                // row group

    float acc[8][8];
#pragma unroll
    for (int i = 0; i < 8; i++)
#pragma unroll
        for (int j = 0; j < 8; j++) acc[i][j] = 0.0f;

    for (int k0 = 0; k0 < K; k0 += BK) {
        // A tile load (transpose into As[k][m])
        float4 av = *(const float4*)(Ab + (size_t)(m0 + aRow) * K + k0 + aSeg);
        As[aSeg + 0][aRow] = av.x;
        As[aSeg + 1][aRow] = av.y;
        As[aSeg + 2][aRow] = av.z;
        As[aSeg + 3][aRow] = av.w;
        // B tile load (direct)
        float4 bv = *(const float4*)(Bb + (size_t)(k0 + bRow) * N + n0 + bCol);
        *(float4*)(&Bs[bRow][bCol]) = bv;
        __syncthreads();

#pragma unroll
        for (int kk = 0; kk < BK; kk++) {
            float a[8], b[8];
#pragma unroll
            for (int i = 0; i < 8; i++) a[i] = As[kk][ty * 8 + i];
#pragma unroll
            for (int j = 0; j < 8; j++) b[j] = Bs[kk][tx * 8 + j];
#pragma unroll
            for (int i = 0; i < 8; i++)
#pragma unroll
                for (int j = 0; j < 8; j++)
                    acc[i][j] = fmaf(a[i], b[j], acc[i][j]);
        }
        __syncthreads();
    }

#pragma unroll
    for (int i = 0; i < 8; i++) {
        const int m = m0 + ty * 8 + i;
        const float bb = HAS_BIAS ? bias[m] : 0.0f;
        float* crow = Cb + (size_t)m * N + n0 + tx * 8;
        float4 o0 = make_float4(acc[i][0] + bb, acc[i][1] + bb,
                                acc[i][2] + bb, acc[i][3] + bb);
        float4 o1 = make_float4(acc[i][4] + bb, acc[i][5] + bb,
                                acc[i][6] + bb, acc[i][7] + bb);
        *(float4*)(crow + 0) = o0;
        *(float4*)(crow + 4) = o1;
    }
}

// ---------------------------------------------------------------------------
// NT GEMM: C[m,n] = scale * sum_k A[m,k] * B[n,k]
// A: M x K row-major (lda = K), B: N x K row-major (ldb = K), C: M x N (ldc = N)
// ---------------------------------------------------------------------------
__global__ __launch_bounds__(256, 2) void gemm_nt_kernel(
    const float* __restrict__ A, size_t strideA,
    const float* __restrict__ Bm, size_t strideB,
    float* __restrict__ Cm, size_t strideC,
    float scale, int M, int N, int K)
{
    const float* Ab = A + (size_t)blockIdx.z * strideA;
    const float* Bb = Bm + (size_t)blockIdx.z * strideB;
    float*       Cb = Cm + (size_t)blockIdx.z * strideC;

    __shared__ float As[BK][BM + PAD];
    __shared__ float Bs[BK][BN + PAD];

    const int tid = threadIdx.x;
    const int m0 = blockIdx.y * BM;
    const int n0 = blockIdx.x * BN;

    const int row = tid >> 1;               // 0..127
    const int seg = (tid & 1) * 4;          // 0 or 4
    const int tx = tid & 15;
    const int ty = tid >> 4;

    float acc[8][8];
#pragma unroll
    for (int i = 0; i < 8; i++)
#pragma unroll
        for (int j = 0; j < 8; j++) acc[i][j] = 0.0f;

    for (int k0 = 0; k0 < K; k0 += BK) {
        float4 av = *(const float4*)(Ab + (size_t)(m0 + row) * K + k0 + seg);
        float4 bv = *(const float4*)(Bb + (size_t)(n0 + row) * K + k0 + seg);
        As[seg + 0][row] = av.x; As[seg + 1][row] = av.y;
        As[seg + 2][row] = av.z; As[seg + 3][row] = av.w;
        Bs[seg + 0][row] = bv.x; Bs[seg + 1][row] = bv.y;
        Bs[seg + 2][row] = bv.z; Bs[seg + 3][row] = bv.w;
        __syncthreads();

#pragma unroll
        for (int kk = 0; kk < BK; kk++) {
            float a[8], b[8];
#pragma unroll
            for (int i = 0; i < 8; i++) a[i] = As[kk][ty * 8 + i];
#pragma unroll
            for (int j = 0; j < 8; j++) b[j] = Bs[kk][tx * 8 + j];
#pragma unroll
            for (int i = 0; i < 8; i++)
#pragma unroll
                for (int j = 0; j < 8; j++)
                    acc[i][j] = fmaf(a[i], b[j], acc[i][j]);
        }
        __syncthreads();
    }

#pragma unroll
    for (int i = 0; i < 8; i++) {
        const int m = m0 + ty * 8 + i;
        float* crow = Cb + (size_t)m * N + n0 + tx * 8;
        float4 o0 = make_float4(acc[i][0] * scale, acc[i][1] * scale,
                                acc[i][2] * scale, acc[i][3] * scale);
        float4 o1 = make_float4(acc[i][4] * scale, acc[i][5] * scale,
                                acc[i][6] * scale, acc[i][7] * scale);
        *(float4*)(crow + 0) = o0;
        *(float4*)(crow + 4) = o1;
    }
}

// ---------------------------------------------------------------------------
// Row softmax over 512-element rows; one warp per row (in place).
// ---------------------------------------------------------------------------
__global__ void softmax_kernel(float* __restrict__ d, int rows)
{
    const int gw = (blockIdx.x * blockDim.x + threadIdx.x) >> 5;
    if (gw >= rows) return;
    const int lane = threadIdx.x & 31;
    float4* r = (float4*)(d + (size_t)gw * CC);

    float4 v[4];
    float mx = -1e30f;
#pragma unroll
    for (int i = 0; i < 4; i++) {
        v[i] = r[lane + 32 * i];
        mx = fmaxf(mx, fmaxf(fmaxf(v[i].x, v[i].y), fmaxf(v[i].z, v[i].w)));
    }
#pragma unroll
    for (int o = 16; o > 0; o >>= 1)
        mx = fmaxf(mx, __shfl_xor_sync(0xffffffffu, mx, o));

    float s = 0.0f;
#pragma unroll
    for (int i = 0; i < 4; i++) {
        v[i].x = expf(v[i].x - mx);
        v[i].y = expf(v[i].y - mx);
        v[i].z = expf(v[i].z - mx);
        v[i].w = expf(v[i].w - mx);
        s += v[i].x + v[i].y + v[i].z + v[i].w;
    }
#pragma unroll
    for (int o = 16; o > 0; o >>= 1)
        s += __shfl_xor_sync(0xffffffffu, s, o);

    const float inv = 1.0f / s;
#pragma unroll
    for (int i = 0; i < 4; i++) {
        v[i].x *= inv; v[i].y *= inv; v[i].z *= inv; v[i].w *= inv;
        r[lane + 32 * i] = v[i];
    }
}

// ---------------------------------------------------------------------------
// Launch: q,k,v proj (3x NN GEMM) -> dots (NT) -> softmax -> out (NN)
// Inputs (metadata order): x, Wq, bq, Wk, bk, Wv, bv
// ---------------------------------------------------------------------------
extern "C" void kernel_launch(void* const* d_in, const int* in_sizes, int n_in,
                              void* d_out, int out_size)
{
    (void)in_sizes; (void)n_in; (void)out_size;
    const float* x  = (const float*)d_in[0];
    const float* Wq = (const float*)d_in[1];
    const float* bq = (const float*)d_in[2];
    const float* Wk = (const float*)d_in[3];
    const float* bk = (const float*)d_in[4];
    const float* Wv = (const float*)d_in[5];
    const float* bv = (const float*)d_in[6];
    float* out = (float*)d_out;

    float *q, *k, *v, *dots;
    cudaGetSymbolAddress((void**)&q, g_q);
    cudaGetSymbolAddress((void**)&k, g_k);
    cudaGetSymbolAddress((void**)&v, g_v);
    cudaGetSymbolAddress((void**)&dots, g_dots);

    const size_t CT = (size_t)CC * TT;   // per-batch q/k/v/x/out stride
    const size_t CCs = (size_t)CC * CC;  // per-batch dots stride

    dim3 blk(256);

    // QKV projections: M=512 (o), N=4096 (t), K=512 (c); A=W shared across batch
    dim3 gProj(TT / BN, CC / BM, BB);    // (32, 4, 8)
    gemm_nn_kernel<true><<<gProj, blk>>>(Wq, 0, x, CT, q, CT, bq, CC, TT, CC);
    gemm_nn_kernel<true><<<gProj, blk>>>(Wk, 0, x, CT, k, CT, bk, CC, TT, CC);
    gemm_nn_kernel<true><<<gProj, blk>>>(Wv, 0, x, CT, v, CT, bv, CC, TT, CC);

    // dots = SCALE * q @ k^T per batch: M=512, N=512, K=4096
    dim3 gDots(CC / BN, CC / BM, BB);    // (4, 4, 8)
    gemm_nt_kernel<<<gDots, blk>>>(q, CT, k, CT, dots, CCs, SCALE_F, CC, CC, TT);

    // softmax over last axis: 8*512 rows of 512
    {
        int rows = BB * CC;              // 4096
        int threads = 128;               // 4 warps -> 4 rows per block
        int grid = rows / 4;             // 1024
        softmax_kernel<<<grid, threads>>>(dots, rows);
    }

    // out = attn @ v per batch: M=512 (c), N=4096 (t), K=512 (d)
    dim3 gOut(TT / BN, CC / BM, BB);     // (32, 4, 8)
    gemm_nn_kernel<false><<<gOut, blk>>>(dots, CCs, v, CT, out, CT, nullptr, CC, TT, CC);
}